// round 4
// baseline (speedup 1.0000x reference)
#include <cuda_runtime.h>
#include <math.h>

typedef unsigned long long ull;

#define MAXN_PAD 75008   // 586 blocks * 128 rows

// Global scratch (static __device__ arrays: zero-initialized, never allocated)
__device__ float g_agg[(size_t)MAXN_PAD * 512];   // 153.6 MB
__device__ float g_h  [(size_t)MAXN_PAD * 64];    // 19.2 MB
__device__ float g_wt1[64 * 512];                 // W1^T  [c][k]
__device__ float g_wt2[40 * 512];                 // W2^T  [c][k]

__device__ __forceinline__ void upk2(ull v, float& x, float& y) {
    asm("mov.b64 {%0, %1}, %2;" : "=f"(x), "=f"(y) : "l"(v));
}
__device__ __forceinline__ void ffma2(ull& d, ull a, ull b) {
    asm("fma.rn.f32x2 %0, %1, %2, %0;" : "+l"(d) : "l"(a), "l"(b));
}
__device__ __forceinline__ void fadd2(ull& d, ull a) {
    asm("add.rn.f32x2 %0, %0, %1;" : "+l"(d) : "l"(a));
}

// ---------------------------------------------------------------------------
// W transpose:  wt[c*512 + k] = W[k*F + c]
// ---------------------------------------------------------------------------
__global__ void wt_kernel(const float* __restrict__ W1,
                          const float* __restrict__ W2,
                          float* __restrict__ wt1,
                          float* __restrict__ wt2)
{
    int i = blockIdx.x * blockDim.x + threadIdx.x;
    if (i < 64 * 512) {
        int c = i >> 9, k = i & 511;
        wt1[i] = W1[k * 64 + c];
    }
    if (i < 40 * 512) {
        int c = i / 512, k = i % 512;
        wt2[i] = W2[k * 40 + c];
    }
}

// ---------------------------------------------------------------------------
// Aggregation: one warp per node.  agg[node][r*64 + d] = sum_{e:rel=r} x[src_e][d]
// Ballot-per-relation: one unconditional f32x2 add per edge.
// ---------------------------------------------------------------------------
__global__ void __launch_bounds__(256)
agg_kernel(const float* __restrict__ xin,    // [n][64]
           const int*   __restrict__ ptr,
           const int*   __restrict__ idx,
           const int*   __restrict__ rel,
           float*       __restrict__ agg,    // [MAXN_PAD][512]
           int n)
{
    const int node = (blockIdx.x * blockDim.x + threadIdx.x) >> 5;
    const int lane = threadIdx.x & 31;
    if (node >= n) return;

    ull acc[8];
    #pragma unroll
    for (int r = 0; r < 8; ++r) acc[r] = 0ull;

    const int e0 = ptr[node], e1 = ptr[node + 1];
    for (int eb = e0; eb < e1; eb += 32) {
        const int cnt = min(32, e1 - eb);
        int mi = 0, mr = -1;
        if (lane < cnt) { mi = idx[eb + lane]; mr = rel[eb + lane]; }
        #pragma unroll
        for (int r = 0; r < 8; ++r) {
            unsigned m = __ballot_sync(0xffffffffu, mr == r);
            while (m) {
                int t = __ffs(m) - 1; m &= m - 1;
                int s = __shfl_sync(0xffffffffu, mi, t);
                ull v = *(const ull*)(xin + (size_t)s * 64 + 2 * lane);
                fadd2(acc[r], v);
            }
        }
    }

    float* arow = agg + (size_t)node * 512;
    #pragma unroll
    for (int r = 0; r < 8; ++r)
        *(ull*)(arow + r * 64 + 2 * lane) = acc[r];
}

// ---------------------------------------------------------------------------
// GEMM layer 1:  H[g][c] = relu( sum_k A[g][k] * W[k][c] ),  F=64
// 256 threads, 128 rows/block, thread tile 8 rows x 4 cols, k-pair FFMA2.
// lo half of each acc sums even pair slots, hi sums odd; lo+hi at the end.
// ---------------------------------------------------------------------------
__global__ void __launch_bounds__(256, 1)
gemm1_kernel(const float* __restrict__ A,    // [MAXN_PAD][512]
             const float* __restrict__ BT,   // [64][512]  (W^T)
             float*       __restrict__ H,    // [MAXN_PAD][64]
             int n)
{
    const int tid  = threadIdx.x;
    const int rg   = tid >> 4;               // 0..15 -> 8 rows each
    const int cg   = tid & 15;               // 0..15 -> 4 cols each
    const int row0 = blockIdx.x * 128 + rg * 8;

    const float* a = A  + (size_t)row0 * 512;
    const float* b = BT + (size_t)cg * 4 * 512;

    ull acc[8][4];
    #pragma unroll
    for (int j = 0; j < 8; ++j)
        #pragma unroll
        for (int c = 0; c < 4; ++c) acc[j][c] = 0ull;

    #pragma unroll 2
    for (int k = 0; k < 512; k += 4) {
        ull av0[8], av1[8], bv0[4], bv1[4];
        #pragma unroll
        for (int c = 0; c < 4; ++c) {
            ulonglong2 t = *(const ulonglong2*)(b + (size_t)c * 512 + k);
            bv0[c] = t.x; bv1[c] = t.y;
        }
        #pragma unroll
        for (int j = 0; j < 8; ++j) {
            ulonglong2 t = *(const ulonglong2*)(a + (size_t)j * 512 + k);
            av0[j] = t.x; av1[j] = t.y;
        }
        #pragma unroll
        for (int j = 0; j < 8; ++j)
            #pragma unroll
            for (int c = 0; c < 4; ++c) {
                ffma2(acc[j][c], av0[j], bv0[c]);
                ffma2(acc[j][c], av1[j], bv1[c]);
            }
    }

    #pragma unroll
    for (int j = 0; j < 8; ++j) {
        int g = row0 + j;
        if (g < n) {
            float lo, hi;
            float4 o;
            upk2(acc[j][0], lo, hi); o.x = fmaxf(lo + hi, 0.f);
            upk2(acc[j][1], lo, hi); o.y = fmaxf(lo + hi, 0.f);
            upk2(acc[j][2], lo, hi); o.z = fmaxf(lo + hi, 0.f);
            upk2(acc[j][3], lo, hi); o.w = fmaxf(lo + hi, 0.f);
            *(float4*)(H + (size_t)g * 64 + cg * 4) = o;
        }
    }
}

// ---------------------------------------------------------------------------
// GEMM layer 2 + log_softmax:  out[g][c] = logsoftmax_c( sum_k A[g][k]*W[k][c] )
// F=40.  256 threads, 128 rows/block, thread tile 4 rows x 5 cols.
// ---------------------------------------------------------------------------
__global__ void __launch_bounds__(256, 1)
gemm2_kernel(const float* __restrict__ A,    // [MAXN_PAD][512]
             const float* __restrict__ BT,   // [40][512]
             float*       __restrict__ out,  // [n][40]
             int n)
{
    __shared__ float so[128 * 41];

    const int tid   = threadIdx.x;
    const int rg    = tid >> 3;              // 0..31 -> 4 rows each
    const int cg    = tid & 7;               // 0..7  -> 5 cols each
    const int lrow0 = rg * 4;
    const int row0  = blockIdx.x * 128 + lrow0;

    const float* a = A  + (size_t)row0 * 512;
    const float* b = BT + (size_t)cg * 5 * 512;

    ull acc[4][5];
    #pragma unroll
    for (int j = 0; j < 4; ++j)
        #pragma unroll
        for (int c = 0; c < 5; ++c) acc[j][c] = 0ull;

    #pragma unroll 2
    for (int k = 0; k < 512; k += 4) {
        ull av0[4], av1[4], bv0[5], bv1[5];
        #pragma unroll
        for (int c = 0; c < 5; ++c) {
            ulonglong2 t = *(const ulonglong2*)(b + (size_t)c * 512 + k);
            bv0[c] = t.x; bv1[c] = t.y;
        }
        #pragma unroll
        for (int j = 0; j < 4; ++j) {
            ulonglong2 t = *(const ulonglong2*)(a + (size_t)j * 512 + k);
            av0[j] = t.x; av1[j] = t.y;
        }
        #pragma unroll
        for (int j = 0; j < 4; ++j)
            #pragma unroll
            for (int c = 0; c < 5; ++c) {
                ffma2(acc[j][c], av0[j], bv0[c]);
                ffma2(acc[j][c], av1[j], bv1[c]);
            }
    }

    #pragma unroll
    for (int j = 0; j < 4; ++j)
        #pragma unroll
        for (int c = 0; c < 5; ++c) {
            float lo, hi; upk2(acc[j][c], lo, hi);
            so[(lrow0 + j) * 41 + cg * 5 + c] = lo + hi;
        }
    __syncthreads();

    // log-softmax: each warp handles 16 rows
    const int warp = tid >> 5;
    const int lane = tid & 31;
    for (int rr = warp * 16; rr < warp * 16 + 16; ++rr) {
        float v1 = (lane < 40) ? so[rr * 41 + lane]      : -INFINITY;
        float v2 = (lane < 8)  ? so[rr * 41 + 32 + lane] : -INFINITY;
        float m = fmaxf(v1, v2);
        #pragma unroll
        for (int o = 16; o; o >>= 1)
            m = fmaxf(m, __shfl_xor_sync(0xffffffffu, m, o));
        float s = ((lane < 40) ? expf(v1 - m) : 0.f)
                + ((lane < 8)  ? expf(v2 - m) : 0.f);
        #pragma unroll
        for (int o = 16; o; o >>= 1)
            s += __shfl_xor_sync(0xffffffffu, s, o);
        float lse = m + logf(s);

        int g = blockIdx.x * 128 + rr;
        if (g < n) {
            if (lane < 40) out[(size_t)g * 40 + lane]      = v1 - lse;
            if (lane < 8)  out[(size_t)g * 40 + 32 + lane] = v2 - lse;
        }
    }
}

// ---------------------------------------------------------------------------
extern "C" void kernel_launch(void* const* d_in, const int* in_sizes, int n_in,
                              void* d_out, int out_size)
{
    const float* x   = (const float*)d_in[0];
    const int*   ptr = (const int*)  d_in[1];
    const int*   idx = (const int*)  d_in[2];
    const int*   rel = (const int*)  d_in[3];
    const float* W1  = (const float*)d_in[4];
    const float* W2  = (const float*)d_in[5];
    float* out = (float*)d_out;

    const int n = in_sizes[1] - 1;

    float *agg, *h, *wt1, *wt2;
    cudaGetSymbolAddress((void**)&agg, g_agg);
    cudaGetSymbolAddress((void**)&h,   g_h);
    cudaGetSymbolAddress((void**)&wt1, g_wt1);
    cudaGetSymbolAddress((void**)&wt2, g_wt2);

    const int agg_grid  = (n + 7) / 8;          // 8 warps (nodes) per 256-thr block
    const int gemm_grid = (n + 127) / 128;

    wt_kernel<<<(64 * 512 + 255) / 256, 256>>>(W1, W2, wt1, wt2);
    agg_kernel<<<agg_grid, 256>>>(x, ptr, idx, rel, agg, n);
    gemm1_kernel<<<gemm_grid, 256>>>(agg, wt1, h, n);
    agg_kernel<<<agg_grid, 256>>>(h, ptr, idx, rel, agg, n);
    gemm2_kernel<<<gemm_grid, 256>>>(agg, wt2, out, n);
}

// round 5
// speedup vs baseline: 1.9960x; 1.9960x over previous
#include <cuda_runtime.h>
#include <math.h>

typedef unsigned long long ull;

#define MAXN_PAD 75008   // 586 blocks * 128 rows

// Global scratch (static __device__ arrays: never allocated at runtime)
__device__ float g_agg[(size_t)MAXN_PAD * 512];   // 153.6 MB
__device__ float g_h  [(size_t)MAXN_PAD * 64];    // 19.2 MB  (rows >= n stay 0)

__device__ __forceinline__ ull pk2(float x, float y) {
    ull r; asm("mov.b64 %0, {%1, %2};" : "=l"(r) : "f"(x), "f"(y)); return r;
}
__device__ __forceinline__ void upk2(ull v, float& x, float& y) {
    asm("mov.b64 {%0, %1}, %2;" : "=f"(x), "=f"(y) : "l"(v));
}
__device__ __forceinline__ void ffma2(ull& d, ull a, ull b) {
    asm("fma.rn.f32x2 %0, %1, %2, %0;" : "+l"(d) : "l"(a), "l"(b));
}
__device__ __forceinline__ void fadd2(ull& d, ull a) {
    asm("add.rn.f32x2 %0, %0, %1;" : "+l"(d) : "l"(a));
}

// ---------------------------------------------------------------------------
// Aggregation: one warp per node.  agg[node][r*64+d] = sum_{e: rel_e=r} x[src_e][d]
// ---------------------------------------------------------------------------
__global__ void __launch_bounds__(256)
agg_kernel(const float* __restrict__ xin,
           const int*   __restrict__ ptr,
           const int*   __restrict__ idx,
           const int*   __restrict__ rel,
           float*       __restrict__ agg,
           int n)
{
    const int node = (blockIdx.x * blockDim.x + threadIdx.x) >> 5;
    const int lane = threadIdx.x & 31;
    if (node >= n) return;

    ull acc[8];
    #pragma unroll
    for (int r = 0; r < 8; ++r) acc[r] = 0ull;

    const int e0 = ptr[node], e1 = ptr[node + 1];
    for (int eb = e0; eb < e1; eb += 32) {
        const int cnt = min(32, e1 - eb);
        int mi = 0, mr = -1;
        if (lane < cnt) { mi = idx[eb + lane]; mr = rel[eb + lane]; }
        #pragma unroll
        for (int r = 0; r < 8; ++r) {
            unsigned m = __ballot_sync(0xffffffffu, mr == r);
            while (m) {
                int t = __ffs(m) - 1; m &= m - 1;
                int s = __shfl_sync(0xffffffffu, mi, t);
                ull v = *(const ull*)(xin + (size_t)s * 64 + 2 * lane);
                fadd2(acc[r], v);
            }
        }
    }

    float* arow = agg + (size_t)node * 512;
    #pragma unroll
    for (int r = 0; r < 8; ++r)
        *(ull*)(arow + r * 64 + 2 * lane) = acc[r];
}

// ---------------------------------------------------------------------------
// GEMM layer 1: H = relu(A @ W), A [MAXN_PAD][512], W [512][64] (k-major).
// 128 rows/block, 256 threads, thread tile 8x4, double-buffered SMEM.
// ---------------------------------------------------------------------------
#define AST 68   // A smem row stride (floats): 16B-aligned rows, bank spread

__global__ void __launch_bounds__(256, 2)
gemm1_kernel(const float* __restrict__ A,
             const float* __restrict__ W,    // [512][64]
             float*       __restrict__ H,    // [MAXN_PAD][64]
             int n)
{
    extern __shared__ float sm[];
    float* As = sm;                       // [2][128*AST]
    float* Bs = sm + 2 * 128 * AST;       // [2][64*64]  k-major

    const int tid = threadIdx.x;
    const int rg  = tid >> 4;             // 16 groups of 8 rows
    const int cg  = tid & 15;             // 16 groups of 4 cols
    const size_t row0 = (size_t)blockIdx.x * 128;

    // ldg+sts of one k-chunk (64 k) into buffer `buf`
    auto stage = [&](int k0, int buf) {
        float* as = As + buf * 128 * AST;
        float* bs = Bs + buf * 64 * 64;
        #pragma unroll
        for (int i = 0; i < 8; ++i) {                 // A: 2048 float4
            int v = tid + i * 256;
            int r = v >> 4, c4 = v & 15;
            float4 t = *(const float4*)(A + (row0 + r) * 512 + k0 + 4 * c4);
            *(float4*)(as + r * AST + 4 * c4) = t;
        }
        #pragma unroll
        for (int i = 0; i < 4; ++i) {                 // W: 1024 float4
            int v = tid + i * 256;
            int kk = v >> 4, c4 = v & 15;
            float4 t = *(const float4*)(W + (size_t)(k0 + kk) * 64 + 4 * c4);
            *(float4*)(bs + kk * 64 + 4 * c4) = t;
        }
    };

    ull acc[8][4];
    #pragma unroll
    for (int j = 0; j < 8; ++j)
        #pragma unroll
        for (int c = 0; c < 4; ++c) acc[j][c] = 0ull;

    stage(0, 0);
    __syncthreads();

    #pragma unroll 1
    for (int ch = 0; ch < 8; ++ch) {
        const int buf = ch & 1;
        if (ch < 7) stage((ch + 1) * 64, buf ^ 1);

        const float* as = As + buf * 128 * AST + rg * 8 * AST;
        const float* bs = Bs + buf * 64 * 64 + 4 * cg;
        #pragma unroll 8
        for (int kp = 0; kp < 32; ++kp) {
            float4 b0 = *(const float4*)(bs + (2 * kp) * 64);
            float4 b1 = *(const float4*)(bs + (2 * kp + 1) * 64);
            ull bb0 = pk2(b0.x, b1.x), bb1 = pk2(b0.y, b1.y);
            ull bb2 = pk2(b0.z, b1.z), bb3 = pk2(b0.w, b1.w);
            #pragma unroll
            for (int j = 0; j < 8; ++j) {
                ull a = *(const ull*)(as + j * AST + 2 * kp);
                ffma2(acc[j][0], a, bb0);
                ffma2(acc[j][1], a, bb1);
                ffma2(acc[j][2], a, bb2);
                ffma2(acc[j][3], a, bb3);
            }
        }
        __syncthreads();
    }

    #pragma unroll
    for (int j = 0; j < 8; ++j) {
        float lo, hi; float4 o;
        upk2(acc[j][0], lo, hi); o.x = fmaxf(lo + hi, 0.f);
        upk2(acc[j][1], lo, hi); o.y = fmaxf(lo + hi, 0.f);
        upk2(acc[j][2], lo, hi); o.z = fmaxf(lo + hi, 0.f);
        upk2(acc[j][3], lo, hi); o.w = fmaxf(lo + hi, 0.f);
        *(float4*)(H + (row0 + rg * 8 + j) * 64 + 4 * cg) = o;  // padded, unguarded
    }
}

// ---------------------------------------------------------------------------
// GEMM layer 2 + log_softmax: out = logsoftmax(A @ W), W [512][40] k-major.
// 128 rows/block, 256 threads, thread tile 4x5.
// ---------------------------------------------------------------------------
__global__ void __launch_bounds__(256, 2)
gemm2_kernel(const float* __restrict__ A,
             const float* __restrict__ W,    // [512][40]
             float*       __restrict__ out,  // [n][40]
             int n)
{
    extern __shared__ float sm[];
    float* As = sm;                        // [2][128*AST]
    float* Bs = sm + 2 * 128 * AST;        // [2][64*40]
    float* so = Bs + 2 * 64 * 40;          // [128][41]

    const int tid = threadIdx.x;
    const int rg  = tid >> 3;              // 32 groups of 4 rows
    const int cg  = tid & 7;               // 8 groups of 5 cols
    const size_t row0 = (size_t)blockIdx.x * 128;

    auto stage = [&](int k0, int buf) {
        float* as = As + buf * 128 * AST;
        float* bs = Bs + buf * 64 * 40;
        #pragma unroll
        for (int i = 0; i < 8; ++i) {
            int v = tid + i * 256;
            int r = v >> 4, c4 = v & 15;
            float4 t = *(const float4*)(A + (row0 + r) * 512 + k0 + 4 * c4);
            *(float4*)(as + r * AST + 4 * c4) = t;
        }
        #pragma unroll
        for (int i = 0; i < 5; ++i) {                 // W chunk: 1280 float2
            int v = tid + i * 256;
            int kk = v / 20, c2 = v % 20;
            float2 t = *(const float2*)(W + (size_t)(k0 + kk) * 40 + 2 * c2);
            *(float2*)(bs + kk * 40 + 2 * c2) = t;
        }
    };

    ull acc[4][5];
    #pragma unroll
    for (int j = 0; j < 4; ++j)
        #pragma unroll
        for (int c = 0; c < 5; ++c) acc[j][c] = 0ull;

    stage(0, 0);
    __syncthreads();

    #pragma unroll 1
    for (int ch = 0; ch < 8; ++ch) {
        const int buf = ch & 1;
        if (ch < 7) stage((ch + 1) * 64, buf ^ 1);

        const float* as = As + buf * 128 * AST + rg * 4 * AST;
        const float* bs = Bs + buf * 64 * 40 + 5 * cg;
        #pragma unroll 8
        for (int kp = 0; kp < 32; ++kp) {
            const float* b0 = bs + (2 * kp) * 40;
            const float* b1 = b0 + 40;
            ull bb[5];
            #pragma unroll
            for (int c = 0; c < 5; ++c) bb[c] = pk2(b0[c], b1[c]);
            #pragma unroll
            for (int j = 0; j < 4; ++j) {
                ull a = *(const ull*)(as + j * AST + 2 * kp);
                #pragma unroll
                for (int c = 0; c < 5; ++c) ffma2(acc[j][c], a, bb[c]);
            }
        }
        __syncthreads();
    }

    #pragma unroll
    for (int j = 0; j < 4; ++j)
        #pragma unroll
        for (int c = 0; c < 5; ++c) {
            float lo, hi; upk2(acc[j][c], lo, hi);
            so[(rg * 4 + j) * 41 + cg * 5 + c] = lo + hi;
        }
    __syncthreads();

    // log-softmax: each warp handles 16 rows
    const int warp = tid >> 5;
    const int lane = tid & 31;
    for (int rr = warp * 16; rr < warp * 16 + 16; ++rr) {
        float v1 = (lane < 40) ? so[rr * 41 + lane]      : -INFINITY;
        float v2 = (lane < 8)  ? so[rr * 41 + 32 + lane] : -INFINITY;
        float m = fmaxf(v1, v2);
        #pragma unroll
        for (int o = 16; o; o >>= 1)
            m = fmaxf(m, __shfl_xor_sync(0xffffffffu, m, o));
        float s = ((lane < 40) ? expf(v1 - m) : 0.f)
                + ((lane < 8)  ? expf(v2 - m) : 0.f);
        #pragma unroll
        for (int o = 16; o; o >>= 1)
            s += __shfl_xor_sync(0xffffffffu, s, o);
        float lse = m + logf(s);

        size_t g = row0 + rr;
        if (g < (size_t)n) {
            if (lane < 40) out[g * 40 + lane]      = v1 - lse;
            if (lane < 8)  out[g * 40 + 32 + lane] = v2 - lse;
        }
    }
}

// ---------------------------------------------------------------------------
extern "C" void kernel_launch(void* const* d_in, const int* in_sizes, int n_in,
                              void* d_out, int out_size)
{
    const float* x   = (const float*)d_in[0];
    const int*   ptr = (const int*)  d_in[1];
    const int*   idx = (const int*)  d_in[2];
    const int*   rel = (const int*)  d_in[3];
    const float* W1  = (const float*)d_in[4];   // [512][64]
    const float* W2  = (const float*)d_in[5];   // [512][40]
    float* out = (float*)d_out;

    const int n = in_sizes[1] - 1;

    float *agg, *h;
    cudaGetSymbolAddress((void**)&agg, g_agg);
    cudaGetSymbolAddress((void**)&h,   g_h);

    const int agg_grid  = (n + 7) / 8;
    const int gemm_grid = (n + 127) / 128;

    const int s1 = (2 * 128 * AST + 2 * 64 * 64) * (int)sizeof(float);            // 102400
    const int s2 = (2 * 128 * AST + 2 * 64 * 40 + 128 * 41) * (int)sizeof(float); // 111104
    static bool attr_done = false;
    if (!attr_done) {
        cudaFuncSetAttribute(gemm1_kernel, cudaFuncAttributeMaxDynamicSharedMemorySize, s1);
        cudaFuncSetAttribute(gemm2_kernel, cudaFuncAttributeMaxDynamicSharedMemorySize, s2);
        attr_done = true;
    }

    agg_kernel<<<agg_grid, 256>>>(x, ptr, idx, rel, agg, n);
    gemm1_kernel<<<gemm_grid, 256, s1>>>(agg, W1, h, n);
    agg_kernel<<<agg_grid, 256>>>(h, ptr, idx, rel, agg, n);
    gemm2_kernel<<<gemm_grid, 256, s2>>>(agg, W2, out, n);
}

// round 7
// speedup vs baseline: 2.3983x; 1.2016x over previous
#include <cuda_runtime.h>
#include <math.h>

typedef unsigned long long ull;
typedef unsigned int u32;

#define MAXN_PAD 75008   // 586 blocks * 128 rows

// Global scratch (static __device__ arrays: never allocated at runtime)
__device__ float g_agg[(size_t)MAXN_PAD * 512];   // 153.6 MB
__device__ float g_h  [(size_t)MAXN_PAD * 64];    // 19.2 MB

__device__ __forceinline__ void upk2(ull v, float& x, float& y) {
    asm("mov.b64 {%0, %1}, %2;" : "=f"(x), "=f"(y) : "l"(v));
}
__device__ __forceinline__ void ffma2(ull& d, ull a, ull b) {
    asm("fma.rn.f32x2 %0, %1, %2, %0;" : "+l"(d) : "l"(a), "l"(b));
}
__device__ __forceinline__ void fadd2(ull& d, ull a) {
    asm("add.rn.f32x2 %0, %0, %1;" : "+l"(d) : "l"(a));
}
__device__ __forceinline__ u32 smem_u32(const void* p) {
    u32 a;
    asm("{ .reg .u64 t; cvta.to.shared.u64 t, %1; cvt.u32.u64 %0, t; }" : "=r"(a) : "l"(p));
    return a;
}
__device__ __forceinline__ void cp16(u32 dst, const void* src) {
    asm volatile("cp.async.cg.shared.global [%0], [%1], 16;" :: "r"(dst), "l"(src));
}
__device__ __forceinline__ void cp_commit() {
    asm volatile("cp.async.commit_group;");
}
__device__ __forceinline__ void cp_wait1() {
    asm volatile("cp.async.wait_group 1;");
}
__device__ __forceinline__ void cp_wait0() {
    asm volatile("cp.async.wait_group 0;");
}

// ---------------------------------------------------------------------------
// Aggregation: one warp per node.  agg[node][r*64+d] = sum_{e: rel_e=r} x[src_e][d]
// ---------------------------------------------------------------------------
__global__ void __launch_bounds__(256)
agg_kernel(const float* __restrict__ xin,
           const int*   __restrict__ ptr,
           const int*   __restrict__ idx,
           const int*   __restrict__ rel,
           float*       __restrict__ agg,
           int n)
{
    const int node = (blockIdx.x * blockDim.x + threadIdx.x) >> 5;
    const int lane = threadIdx.x & 31;
    if (node >= n) return;

    ull acc[8];
    #pragma unroll
    for (int r = 0; r < 8; ++r) acc[r] = 0ull;

    const int e0 = ptr[node], e1 = ptr[node + 1];
    for (int eb = e0; eb < e1; eb += 32) {
        const int cnt = min(32, e1 - eb);
        int mi = 0, mr = -1;
        if (lane < cnt) { mi = idx[eb + lane]; mr = rel[eb + lane]; }
        #pragma unroll
        for (int r = 0; r < 8; ++r) {
            unsigned m = __ballot_sync(0xffffffffu, mr == r);
            while (m) {
                int t = __ffs(m) - 1; m &= m - 1;
                int s = __shfl_sync(0xffffffffu, mi, t);
                ull v = *(const ull*)(xin + (size_t)s * 64 + 2 * lane);
                fadd2(acc[r], v);
            }
        }
    }

    float* arow = agg + (size_t)node * 512;
    #pragma unroll
    for (int r = 0; r < 8; ++r)
        *(ull*)(arow + r * 64 + 2 * lane) = acc[r];
}

// ---------------------------------------------------------------------------
// GEMM layer 1: H = relu(A @ W), A [MAXN_PAD][512] fp32, W [512][64] k-major.
// 128 rows/block, 256 threads, thread tile 8x4.
// A staged via cp.async (2-stage); B pre-packed as k-pair float2 in SMEM.
// ---------------------------------------------------------------------------
#define ASTRIDE 68          // A smem row stride in floats (272B: 16B-mult, bank shift)
#define ABUF    (128 * ASTRIDE)          // floats per A stage (8704)
#define ABYTES  (ABUF * 4)               // 34816

__global__ void __launch_bounds__(256, 2)
gemm1_kernel(const float* __restrict__ A,
             const float* __restrict__ W,    // [512][64]
             float*       __restrict__ H,    // [MAXN_PAD][64]
             int n)
{
    extern __shared__ float sm[];
    float* As = sm;                          // [2][ABUF]
    float* Bs = sm + 2 * ABUF;               // [2][32*64 float2] = [2][4096 floats]
    const u32 asb = smem_u32(As);

    const int tid = threadIdx.x;
    const int rg  = tid >> 4;                // 16 groups of 8 rows
    const int cg  = tid & 15;                // 16 groups of 4 cols
    const size_t row0 = (size_t)blockIdx.x * 128;

    auto cpA = [&](int ch, int buf) {
        #pragma unroll
        for (int i = 0; i < 8; ++i) {
            int v = tid + i * 256;
            int r = v >> 4, c4 = v & 15;
            u32 d = asb + (u32)(buf * ABYTES + (r * ASTRIDE + c4 * 4) * 4);
            cp16(d, A + (row0 + r) * 512 + ch * 64 + c4 * 4);
        }
        cp_commit();
    };

    float2 br[8];
    auto ldgB = [&](int ch) {
        #pragma unroll
        for (int i = 0; i < 8; ++i) {
            int v = tid + i * 256;
            int kp = v >> 6, c = v & 63;
            const float* w = W + (size_t)(ch * 64 + 2 * kp) * 64 + c;
            br[i].x = w[0]; br[i].y = w[64];
        }
    };
    auto stsB = [&](int buf) {
        float* bs = Bs + buf * 4096;
        #pragma unroll
        for (int i = 0; i < 8; ++i) {
            int v = tid + i * 256;
            int kp = v >> 6, c = v & 63;
            *(float2*)(bs + (kp * 64 + c) * 2) = br[i];
        }
    };

    ull acc[8][4];
    #pragma unroll
    for (int j = 0; j < 8; ++j)
        #pragma unroll
        for (int c = 0; c < 4; ++c) acc[j][c] = 0ull;

    // prologue
    cpA(0, 0);
    cpA(1, 1);
    ldgB(0); stsB(0);

    #pragma unroll 1
    for (int ch = 0; ch < 8; ++ch) {
        const int buf = ch & 1;
        if (ch < 7) ldgB(ch + 1);            // LDG early, STS after compute
        if (ch == 7) cp_wait0(); else cp_wait1();
        __syncthreads();

        const float* as = As + buf * ABUF + (rg * 8) * ASTRIDE;
        const float* bs = Bs + buf * 4096 + cg * 8;
        #pragma unroll 4
        for (int kp2 = 0; kp2 < 16; ++kp2) {
            ulonglong2 bA = *(const ulonglong2*)(bs + (2 * kp2) * 128);
            ulonglong2 bB = *(const ulonglong2*)(bs + (2 * kp2) * 128 + 4);
            ulonglong2 bC = *(const ulonglong2*)(bs + (2 * kp2 + 1) * 128);
            ulonglong2 bD = *(const ulonglong2*)(bs + (2 * kp2 + 1) * 128 + 4);
            #pragma unroll
            for (int j = 0; j < 8; ++j) {
                ulonglong2 a = *(const ulonglong2*)(as + j * ASTRIDE + kp2 * 4);
                ffma2(acc[j][0], a.x, bA.x); ffma2(acc[j][0], a.y, bC.x);
                ffma2(acc[j][1], a.x, bA.y); ffma2(acc[j][1], a.y, bC.y);
                ffma2(acc[j][2], a.x, bB.x); ffma2(acc[j][2], a.y, bD.x);
                ffma2(acc[j][3], a.x, bB.y); ffma2(acc[j][3], a.y, bD.y);
            }
        }
        __syncthreads();

        if (ch < 7) stsB((ch + 1) & 1);
        if (ch < 6) cpA(ch + 2, buf);
    }

    #pragma unroll
    for (int j = 0; j < 8; ++j) {
        float lo, hi; float4 o;
        upk2(acc[j][0], lo, hi); o.x = fmaxf(lo + hi, 0.f);
        upk2(acc[j][1], lo, hi); o.y = fmaxf(lo + hi, 0.f);
        upk2(acc[j][2], lo, hi); o.z = fmaxf(lo + hi, 0.f);
        upk2(acc[j][3], lo, hi); o.w = fmaxf(lo + hi, 0.f);
        *(float4*)(H + (row0 + rg * 8 + j) * 64 + 4 * cg) = o;  // rows padded
    }
}

// ---------------------------------------------------------------------------
// GEMM layer 2 + log_softmax: out = logsoftmax(A @ W), W [512][40] k-major.
// 128 rows/block, 256 threads, thread tile 4x5.
// ---------------------------------------------------------------------------
__global__ void __launch_bounds__(256, 2)
gemm2_kernel(const float* __restrict__ A,
             const float* __restrict__ W,    // [512][40]
             float*       __restrict__ out,  // [n][40]
             int n)
{
    extern __shared__ float sm[];
    float* As = sm;                          // [2][ABUF]
    float* Bs = sm + 2 * ABUF;               // [2][32*40 float2] = [2][2560 floats]
    float* so = sm;                          // softmax exchange overlays As[0]
    const u32 asb = smem_u32(As);

    const int tid = threadIdx.x;
    const int rg  = tid >> 3;                // 32 groups of 4 rows
    const int cg  = tid & 7;                 // 8 groups of 5 cols
    const size_t row0 = (size_t)blockIdx.x * 128;

    auto cpA = [&](int ch, int buf) {
        #pragma unroll
        for (int i = 0; i < 8; ++i) {
            int v = tid + i * 256;
            int r = v >> 4, c4 = v & 15;
            u32 d = asb + (u32)(buf * ABYTES + (r * ASTRIDE + c4 * 4) * 4);
            cp16(d, A + (row0 + r) * 512 + ch * 64 + c4 * 4);
        }
        cp_commit();
    };

    float2 br[5];
    auto ldgB = [&](int ch) {
        #pragma unroll
        for (int i = 0; i < 5; ++i) {
            int v = tid + i * 256;           // < 1280
            int kp = v / 40, c = v % 40;
            const float* w = W + (size_t)(ch * 64 + 2 * kp) * 40 + c;
            br[i].x = w[0]; br[i].y = w[40];
        }
    };
    auto stsB = [&](int buf) {
        float* bs = Bs + buf * 2560;
        #pragma unroll
        for (int i = 0; i < 5; ++i) {
            int v = tid + i * 256;
            int kp = v / 40, c = v % 40;
            *(float2*)(bs + (kp * 40 + c) * 2) = br[i];
        }
    };

    ull acc[4][5];
    #pragma unroll
    for (int j = 0; j < 4; ++j)
        #pragma unroll
        for (int c = 0; c < 5; ++c) acc[j][c] = 0ull;

    cpA(0, 0);
    cpA(1, 1);
    ldgB(0); stsB(0);

    #pragma unroll 1
    for (int ch = 0; ch < 8; ++ch) {
        const int buf = ch & 1;
        if (ch < 7) ldgB(ch + 1);
        if (ch == 7) cp_wait0(); else cp_wait1();
        __syncthreads();

        const float* as = As + buf * ABUF + (rg * 4) * ASTRIDE;
        const float* bs = Bs + buf * 2560 + cg * 10;
        #pragma unroll 4
        for (int kp2 = 0; kp2 < 16; ++kp2) {
            ull b0[5], b1[5];
            #pragma unroll
            for (int c = 0; c < 5; ++c) {
                b0[c] = *(const ull*)(bs + (2 * kp2) * 80 + 2 * c);
                b1[c] = *(const ull*)(bs + (2 * kp2 + 1) * 80 + 2 * c);
            }
            #pragma unroll
            for (int j = 0; j < 4; ++j) {
                ulonglong2 a = *(const ulonglong2*)(as + j * ASTRIDE + kp2 * 4);
                #pragma unroll
                for (int c = 0; c < 5; ++c) {
                    ffma2(acc[j][c], a.x, b0[c]);
                    ffma2(acc[j][c], a.y, b1[c]);
                }
            }
        }
        __syncthreads();

        if (ch < 7) stsB((ch + 1) & 1);
        if (ch < 6) cpA(ch + 2, buf);
    }

    // partial results -> smem (overlays As[0]; all reads of As done)
    #pragma unroll
    for (int j = 0; j < 4; ++j)
        #pragma unroll
        for (int c = 0; c < 5; ++c) {
            float lo, hi; upk2(acc[j][c], lo, hi);
            so[(rg * 4 + j) * 41 + cg * 5 + c] = lo + hi;
        }
    __syncthreads();

    // log-softmax: each warp handles 16 rows
    const int warp = tid >> 5;
    const int lane = tid & 31;
    for (int rr = warp * 16; rr < warp * 16 + 16; ++rr) {
        float v1 = (lane < 40) ? so[rr * 41 + lane]      : -INFINITY;
        float v2 = (lane < 8)  ? so[rr * 41 + 32 + lane] : -INFINITY;
        float m = fmaxf(v1, v2);
        #pragma unroll
        for (int o = 16; o; o >>= 1)
            m = fmaxf(m, __shfl_xor_sync(0xffffffffu, m, o));
        float s = ((lane < 40) ? expf(v1 - m) : 0.f)
                + ((lane < 8)  ? expf(v2 - m) : 0.f);
        #pragma unroll
        for (int o = 16; o; o >>= 1)
            s += __shfl_xor_sync(0xffffffffu, s, o);
        float lse = m + logf(s);

        size_t g = row0 + rr;
        if (g < (size_t)n) {
            if (lane < 40) out[g * 40 + lane]      = v1 - lse;
            if (lane < 8)  out[g * 40 + 32 + lane] = v2 - lse;
        }
    }
}

// ---------------------------------------------------------------------------
extern "C" void kernel_launch(void* const* d_in, const int* in_sizes, int n_in,
                              void* d_out, int out_size)
{
    const float* x   = (const float*)d_in[0];
    const int*   ptr = (const int*)  d_in[1];
    const int*   idx = (const int*)  d_in[2];
    const int*   rel = (const int*)  d_in[3];
    const float* W1  = (const float*)d_in[4];   // [512][64]
    const float* W2  = (const float*)d_in[5];   // [512][40]
    float* out = (float*)d_out;

    const int n = in_sizes[1] - 1;

    float *agg, *h;
    cudaGetSymbolAddress((void**)&agg, g_agg);
    cudaGetSymbolAddress((void**)&h,   g_h);

    const int agg_grid  = (n + 7) / 8;
    const int gemm_grid = (n + 127) / 128;      // 586

    const int s1 = (2 * ABUF + 2 * 4096) * (int)sizeof(float);   // 102400
    const int s2 = (2 * ABUF + 2 * 2560) * (int)sizeof(float);   //  90112
    cudaFuncSetAttribute(gemm1_kernel, cudaFuncAttributeMaxDynamicSharedMemorySize, s1);
    cudaFuncSetAttribute(gemm2_kernel, cudaFuncAttributeMaxDynamicSharedMemorySize, s2);

    agg_kernel<<<agg_grid, 256>>>(x, ptr, idx, rel, agg, n);
    gemm1_kernel<<<gemm_grid, 256, s1>>>(agg, W1, h, n);
    agg_kernel<<<agg_grid, 256>>>(h, ptr, idx, rel, agg, n);
    gemm2_kernel<<<gemm_grid, 256, s2>>>(agg, W2, out, n);
}

// round 8
// speedup vs baseline: 2.7423x; 1.1434x over previous
#include <cuda_runtime.h>
#include <math.h>

typedef unsigned long long ull;
typedef unsigned int u32;

#define MAXN_PAD 75008   // 293 blocks * 256 rows

// Global scratch (static __device__ arrays: never allocated at runtime)
__device__ float g_agg[(size_t)MAXN_PAD * 512];   // 153.6 MB
__device__ float g_h  [(size_t)MAXN_PAD * 64];    // 19.2 MB

__device__ __forceinline__ void upk2(ull v, float& x, float& y) {
    asm("mov.b64 {%0, %1}, %2;" : "=f"(x), "=f"(y) : "l"(v));
}
__device__ __forceinline__ void ffma2(ull& d, ull a, ull b) {
    asm("fma.rn.f32x2 %0, %1, %2, %0;" : "+l"(d) : "l"(a), "l"(b));
}
__device__ __forceinline__ void fadd2(ull& d, ull a) {
    asm("add.rn.f32x2 %0, %0, %1;" : "+l"(d) : "l"(a));
}
__device__ __forceinline__ u32 smem_u32(const void* p) {
    u32 a;
    asm("{ .reg .u64 t; cvta.to.shared.u64 t, %1; cvt.u32.u64 %0, t; }" : "=r"(a) : "l"(p));
    return a;
}
__device__ __forceinline__ void cp16(u32 dst, const void* src) {
    asm volatile("cp.async.cg.shared.global [%0], [%1], 16;" :: "r"(dst), "l"(src));
}
__device__ __forceinline__ void cp_commit() { asm volatile("cp.async.commit_group;"); }
__device__ __forceinline__ void cp_wait1()  { asm volatile("cp.async.wait_group 1;"); }
__device__ __forceinline__ void cp_wait0()  { asm volatile("cp.async.wait_group 0;"); }

// ---------------------------------------------------------------------------
// Aggregation: one warp per node.  agg[node][r*64+d] = sum_{e: rel_e=r} x[src_e][d]
// ---------------------------------------------------------------------------
__global__ void __launch_bounds__(256)
agg_kernel(const float* __restrict__ xin,
           const int*   __restrict__ ptr,
           const int*   __restrict__ idx,
           const int*   __restrict__ rel,
           float*       __restrict__ agg,
           int n)
{
    const int node = (blockIdx.x * blockDim.x + threadIdx.x) >> 5;
    const int lane = threadIdx.x & 31;
    if (node >= n) return;

    ull acc[8];
    #pragma unroll
    for (int r = 0; r < 8; ++r) acc[r] = 0ull;

    const int e0 = ptr[node], e1 = ptr[node + 1];
    for (int eb = e0; eb < e1; eb += 32) {
        const int cnt = min(32, e1 - eb);
        int mi = 0, mr = -1;
        if (lane < cnt) { mi = idx[eb + lane]; mr = rel[eb + lane]; }
        #pragma unroll
        for (int r = 0; r < 8; ++r) {
            unsigned m = __ballot_sync(0xffffffffu, mr == r);
            while (m) {
                int t = __ffs(m) - 1; m &= m - 1;
                int s = __shfl_sync(0xffffffffu, mi, t);
                ull v = *(const ull*)(xin + (size_t)s * 64 + 2 * lane);
                fadd2(acc[r], v);
            }
        }
    }

    float* arow = agg + (size_t)node * 512;
    #pragma unroll
    for (int r = 0; r < 8; ++r)
        *(ull*)(arow + r * 64 + 2 * lane) = acc[r];
}

// ---------------------------------------------------------------------------
// GEMM: out[256 x F] per block = A[256 x 512] @ W[512 x F]
//   256 threads = 8 warps; warp w owns CPW = F/8 columns (broadcast B LDS).
//   lane owns rows {lane + 32j}, j=0..7; thread tile 8 x CPW.
//   A SMEM: [2][256][64] floats with XOR swizzle c4^(row&7) (conflict-free).
//   B SMEM: [2][32][F] k-pair-packed ull.
//   acc ull lanes = (even-k partial, odd-k partial); summed in epilogue.
//   F=64: ReLU -> out (g_h).   F=40: log_softmax -> out.
// ---------------------------------------------------------------------------
template<int F>
__global__ void __launch_bounds__(256, 1)
gemm_kernel(const float* __restrict__ A,
            const float* __restrict__ W,     // [512][F] k-major
            float*       __restrict__ out,
            int n)
{
    constexpr int CPW = F / 8;               // cols per warp: 8 or 5
    extern __shared__ float sm[];
    float* As = sm;                          // [2][16384] floats
    ull*   Bs = (ull*)(sm + 32768);          // [2][32*F] ull
    const u32 asb = smem_u32(As);

    const int tid  = threadIdx.x;
    const int lane = tid & 31;
    const int w    = tid >> 5;
    const size_t row0 = (size_t)blockIdx.x * 256;

    // ---- A chunk staging (cp.async, swizzled) ------------------------------
    auto cpA = [&](int ch, int buf) {
        #pragma unroll
        for (int i = 0; i < 16; ++i) {
            int v  = tid + i * 256;
            int r  = v >> 4, c4 = v & 15;
            u32 d = asb + (u32)((buf * 16384 + r * 64 + ((c4 ^ (r & 7)) << 2)) * 4);
            cp16(d, A + (row0 + r) * 512 + ch * 64 + c4 * 4);
        }
        cp_commit();
    };

    // ---- B chunk staging (k-pair pack via registers) -----------------------
    float2 br[CPW];
    auto ldgB = [&](int ch) {
        #pragma unroll
        for (int i = 0; i < CPW; ++i) {
            int v = tid + i * 256;
            int kp = v / F, c = v % F;
            const float* p = W + (size_t)(ch * 64 + 2 * kp) * F + c;
            br[i].x = p[0]; br[i].y = p[F];
        }
    };
    auto stsB = [&](int buf) {
        ull* bs = Bs + buf * 32 * F;
        #pragma unroll
        for (int i = 0; i < CPW; ++i) {
            int v = tid + i * 256;
            int kp = v / F, c = v % F;
            *(float2*)(bs + kp * F + c) = br[i];
        }
    };

    ull acc[8][CPW];
    #pragma unroll
    for (int j = 0; j < 8; ++j)
        #pragma unroll
        for (int c = 0; c < CPW; ++c) acc[j][c] = 0ull;

    // ---- pipeline prologue --------------------------------------------------
    cpA(0, 0);
    cpA(1, 1);
    ldgB(0); stsB(0);

    #pragma unroll 1
    for (int ch = 0; ch < 8; ++ch) {
        const int buf = ch & 1;
        if (ch < 7) ldgB(ch + 1);
        if (ch == 7) cp_wait0(); else cp_wait1();
        __syncthreads();

        const float* as = As + buf * 16384 + lane * 64;
        const ull*   bs = Bs + buf * 32 * F + w * CPW;
        #pragma unroll
        for (int kp2 = 0; kp2 < 16; ++kp2) {
            ull b0[CPW], b1[CPW];
            #pragma unroll
            for (int c = 0; c < CPW; ++c) {
                b0[c] = bs[(2 * kp2) * F + c];
                b1[c] = bs[(2 * kp2 + 1) * F + c];
            }
            const int swoff = (kp2 ^ (lane & 7)) << 2;
            #pragma unroll
            for (int j = 0; j < 8; ++j) {
                ulonglong2 a = *(const ulonglong2*)(as + j * 2048 + swoff);
                #pragma unroll
                for (int c = 0; c < CPW; ++c) {
                    ffma2(acc[j][c], a.x, b0[c]);
                    ffma2(acc[j][c], a.y, b1[c]);
                }
            }
        }
        __syncthreads();

        if (ch < 7) stsB((ch + 1) & 1);
        if (ch < 6) cpA(ch + 2, buf);
    }

    // ---- epilogue -----------------------------------------------------------
    if (F == 64) {
        // ReLU, direct store (rows padded to 256-multiple; out rows >= n unused)
        #pragma unroll
        for (int j = 0; j < 8; ++j) {
            size_t g = row0 + lane + 32 * j;
            float lo, hi; float4 o;
            upk2(acc[j][0], lo, hi); o.x = fmaxf(lo + hi, 0.f);
            upk2(acc[j][1], lo, hi); o.y = fmaxf(lo + hi, 0.f);
            upk2(acc[j][2], lo, hi); o.z = fmaxf(lo + hi, 0.f);
            upk2(acc[j][3], lo, hi); o.w = fmaxf(lo + hi, 0.f);
            *(float4*)(out + g * 64 + w * 8) = o;
            upk2(acc[j][4], lo, hi); o.x = fmaxf(lo + hi, 0.f);
            upk2(acc[j][5], lo, hi); o.y = fmaxf(lo + hi, 0.f);
            upk2(acc[j][6], lo, hi); o.z = fmaxf(lo + hi, 0.f);
            upk2(acc[j][7], lo, hi); o.w = fmaxf(lo + hi, 0.f);
            *(float4*)(out + g * 64 + w * 8 + 4) = o;
        }
    } else {
        // log_softmax over F=40 columns
        __syncthreads();                       // all done reading As
        float* so = As;                        // [256][41] exchange
        #pragma unroll
        for (int j = 0; j < 8; ++j)
            #pragma unroll
            for (int c = 0; c < CPW; ++c) {
                float lo, hi; upk2(acc[j][c], lo, hi);
                so[(lane + 32 * j) * 41 + w * CPW + c] = lo + hi;
            }
        __syncthreads();

        {   // lane-per-row: warp w handles rows w*32..w*32+31
            const int row = w * 32 + lane;
            float v[40];
            float m = -INFINITY;
            #pragma unroll
            for (int c = 0; c < 40; ++c) { v[c] = so[row * 41 + c]; m = fmaxf(m, v[c]); }
            float s = 0.f;
            #pragma unroll
            for (int c = 0; c < 40; ++c) s += expf(v[c] - m);
            float lse = m + logf(s);
            #pragma unroll
            for (int c = 0; c < 40; ++c) so[row * 41 + c] = v[c] - lse;
        }
        __syncthreads();

        // coalesced copy-out with n-guard
        const int total = (int)min((size_t)256, (size_t)n - row0) * 40;
        for (int e = tid; e < total; e += 256) {
            int r = e / 40, c = e % 40;
            out[row0 * 40 + e] = so[r * 41 + c];
        }
    }
}

// ---------------------------------------------------------------------------
extern "C" void kernel_launch(void* const* d_in, const int* in_sizes, int n_in,
                              void* d_out, int out_size)
{
    const float* x   = (const float*)d_in[0];
    const int*   ptr = (const int*)  d_in[1];
    const int*   idx = (const int*)  d_in[2];
    const int*   rel = (const int*)  d_in[3];
    const float* W1  = (const float*)d_in[4];   // [512][64]
    const float* W2  = (const float*)d_in[5];   // [512][40]
    float* out = (float*)d_out;

    const int n = in_sizes[1] - 1;

    float *agg, *h;
    cudaGetSymbolAddress((void**)&agg, g_agg);
    cudaGetSymbolAddress((void**)&h,   g_h);

    const int agg_grid  = (n + 7) / 8;
    const int gemm_grid = (n + 255) / 256;      // 293

    const int s1 = 32768 * 4 + 2 * 32 * 64 * 8;  // 163840
    const int s2 = 32768 * 4 + 2 * 32 * 40 * 8;  // 151552
    cudaFuncSetAttribute(gemm_kernel<64>, cudaFuncAttributeMaxDynamicSharedMemorySize, s1);
    cudaFuncSetAttribute(gemm_kernel<40>, cudaFuncAttributeMaxDynamicSharedMemorySize, s2);

    agg_kernel<<<agg_grid, 256>>>(x, ptr, idx, rel, agg, n);
    gemm_kernel<64><<<gemm_grid, 256, s1>>>(agg, W1, h, n);
    agg_kernel<<<agg_grid, 256>>>(h, ptr, idx, rel, agg, n);
    gemm_kernel<40><<<gemm_grid, 256, s2>>>(agg, W2, out, n);
}